// round 1
// baseline (speedup 1.0000x reference)
#include <cuda_runtime.h>
#include <math.h>

#define DQ 14
#define HID 32
#define DK 8
#define NS 240
#define DV 256
#define BETA 2.0f

// GEMM tiling
#define BM 128
#define BN 128
#define BK 16
#define TM 8
#define TN 8

// Fallback scratch in case d_out only holds `content` (pitfalls.md: __device__
// globals are the sanctioned scratch mechanism; no runtime allocation allowed).
__device__ float g_attn_scratch[262144 * NS];

// ---------------------------------------------------------------------------
// Kernel 1: projection (14 -> 32 GELU -> 8, L2 normalize) + Hopfield softmax
// One warp per row. 8 warps/block, ROWS_PER_WARP rows each.
// ---------------------------------------------------------------------------
__global__ __launch_bounds__(256) void proj_softmax_kernel(
    const float* __restrict__ query,
    const float* __restrict__ W1, const float* __restrict__ b1,
    const float* __restrict__ W2, const float* __restrict__ b2,
    const float* __restrict__ keys,
    float* __restrict__ attn_out,
    int nrows, int rows_per_warp)
{
    __shared__ float W1_s[HID * DQ];
    __shared__ float b1_s[HID];
    __shared__ float W2_s[DK * HID];
    __shared__ float b2_s[DK];
    __shared__ float keys_s[NS * DK];
    __shared__ float h_s[8][HID];

    const int tid = threadIdx.x;
    for (int i = tid; i < HID * DQ; i += blockDim.x) W1_s[i] = W1[i];
    for (int i = tid; i < HID;      i += blockDim.x) b1_s[i] = b1[i];
    for (int i = tid; i < DK * HID; i += blockDim.x) W2_s[i] = W2[i];
    for (int i = tid; i < DK;       i += blockDim.x) b2_s[i] = b2[i];
    for (int i = tid; i < NS * DK;  i += blockDim.x) keys_s[i] = keys[i];
    __syncthreads();

    const int warp = tid >> 5;
    const int lane = tid & 31;
    const long base_row = ((long)blockIdx.x * 8 + warp) * rows_per_warp;

    for (int rr = 0; rr < rows_per_warp; rr++) {
        const long row = base_row + rr;
        if (row >= nrows) break;

        // Load the 14-d input (uniform across warp -> L1 broadcast)
        const float* x = query + row * DQ;
        float xr[DQ];
        #pragma unroll
        for (int d = 0; d < DQ; d++) xr[d] = __ldg(&x[d]);

        // Hidden layer: lane j computes h_j, exact GELU
        float hj = b1_s[lane];
        #pragma unroll
        for (int d = 0; d < DQ; d++) hj = fmaf(W1_s[lane * DQ + d], xr[d], hj);
        hj = 0.5f * hj * (1.0f + erff(hj * 0.7071067811865476f));
        h_s[warp][lane] = hj;
        __syncwarp();

        // q8 = W2 @ h + b2  (each lane redundantly computes all 8 — cheap)
        float q8[DK];
        #pragma unroll
        for (int i = 0; i < DK; i++) {
            float s = b2_s[i];
            #pragma unroll
            for (int j = 0; j < HID; j++) s = fmaf(W2_s[i * HID + j], h_s[warp][j], s);
            q8[i] = s;
        }
        float nrm = 0.f;
        #pragma unroll
        for (int i = 0; i < DK; i++) nrm = fmaf(q8[i], q8[i], nrm);
        const float inv = 1.0f / fmaxf(sqrtf(nrm), 1e-12f);
        #pragma unroll
        for (int i = 0; i < DK; i++) q8[i] *= inv;

        // sim over 240 keys: lane handles k = lane + 32*t
        float sim[8];
        #pragma unroll
        for (int t = 0; t < 8; t++) {
            const int k = lane + 32 * t;
            float s = -1e30f;
            if (k < NS) {
                s = 0.f;
                #pragma unroll
                for (int i = 0; i < DK; i++) s = fmaf(q8[i], keys_s[k * DK + i], s);
            }
            sim[t] = s;
        }
        float m = sim[0];
        #pragma unroll
        for (int t = 1; t < 8; t++) m = fmaxf(m, sim[t]);
        #pragma unroll
        for (int o = 16; o > 0; o >>= 1) m = fmaxf(m, __shfl_xor_sync(0xffffffffu, m, o));

        float e[8];
        float ssum = 0.f;
        #pragma unroll
        for (int t = 0; t < 8; t++) {
            const int k = lane + 32 * t;
            const float v = (k < NS) ? expf(BETA * (sim[t] - m)) : 0.f;
            e[t] = v;
            ssum += v;
        }
        #pragma unroll
        for (int o = 16; o > 0; o >>= 1) ssum += __shfl_xor_sync(0xffffffffu, ssum, o);
        const float invs = 1.0f / ssum;

        float* arow = attn_out + row * NS;
        #pragma unroll
        for (int t = 0; t < 8; t++) {
            const int k = lane + 32 * t;
            if (k < NS) arow[k] = e[t] * invs;
        }
        __syncwarp();  // protect h_s before next iteration
    }
}

// ---------------------------------------------------------------------------
// Kernel 2: content = attn[N,240] @ values[240,256], classic fp32 SGEMM.
// 128x128 block tile, 16-deep k-panels, 8x8 register tile, 256 threads.
// ---------------------------------------------------------------------------
__global__ __launch_bounds__(256) void content_gemm_kernel(
    const float* __restrict__ attn,
    const float* __restrict__ values,
    float* __restrict__ out,
    int nrows)
{
    __shared__ float As[BK][BM];   // [k][m]
    __shared__ float Bs[BK][BN];   // [k][n]

    const long row0 = (long)blockIdx.y * BM;
    const int  col0 = blockIdx.x * BN;
    const int  tid  = threadIdx.x;
    const int  tx   = tid & 15;    // 16 cols of threads
    const int  ty   = tid >> 4;    // 16 rows of threads

    float acc[TM][TN];
    #pragma unroll
    for (int i = 0; i < TM; i++)
        #pragma unroll
        for (int j = 0; j < TN; j++) acc[i][j] = 0.f;

    for (int k0 = 0; k0 < NS; k0 += BK) {
        // Load attn tile: each thread loads 8 consecutive k of one row (32B)
        {
            const int m = tid >> 1;              // 0..127
            const int kbase = (tid & 1) * 8;     // 0 or 8
            const float* src = attn + (row0 + m) * NS + k0 + kbase;
            #pragma unroll
            for (int u = 0; u < 8; u++) As[kbase + u][m] = src[u];
        }
        // Load values tile: coalesced 128-float rows
        #pragma unroll
        for (int u = 0; u < 8; u++) {
            const int idx = tid + u * 256;
            const int k = idx >> 7, n = idx & 127;
            Bs[k][n] = values[(k0 + k) * DV + col0 + n];
        }
        __syncthreads();

        #pragma unroll
        for (int k = 0; k < BK; k++) {
            float a[TM], b[TN];
            const float4* ap = reinterpret_cast<const float4*>(&As[k][ty * TM]);
            const float4* bp = reinterpret_cast<const float4*>(&Bs[k][tx * TN]);
            float4 a0 = ap[0], a1 = ap[1];
            float4 b0 = bp[0], b1 = bp[1];
            a[0]=a0.x; a[1]=a0.y; a[2]=a0.z; a[3]=a0.w;
            a[4]=a1.x; a[5]=a1.y; a[6]=a1.z; a[7]=a1.w;
            b[0]=b0.x; b[1]=b0.y; b[2]=b0.z; b[3]=b0.w;
            b[4]=b1.x; b[5]=b1.y; b[6]=b1.z; b[7]=b1.w;
            #pragma unroll
            for (int i = 0; i < TM; i++)
                #pragma unroll
                for (int j = 0; j < TN; j++)
                    acc[i][j] = fmaf(a[i], b[j], acc[i][j]);
        }
        __syncthreads();
    }

    #pragma unroll
    for (int i = 0; i < TM; i++) {
        const long r = row0 + ty * TM + i;
        float4* orow = reinterpret_cast<float4*>(out + r * DV + col0 + tx * TN);
        float4 v0 = make_float4(acc[i][0], acc[i][1], acc[i][2], acc[i][3]);
        float4 v1 = make_float4(acc[i][4], acc[i][5], acc[i][6], acc[i][7]);
        orow[0] = v0;
        orow[1] = v1;
    }
}

// ---------------------------------------------------------------------------
extern "C" void kernel_launch(void* const* d_in, const int* in_sizes, int n_in,
                              void* d_out, int out_size)
{
    const float* query  = (const float*)d_in[0];
    const float* W1     = (const float*)d_in[1];
    const float* b1     = (const float*)d_in[2];
    const float* W2     = (const float*)d_in[3];
    const float* b2     = (const float*)d_in[4];
    const float* values = (const float*)d_in[5];
    const float* keys   = (const float*)d_in[6];

    const int nrows = in_sizes[0] / DQ;   // 262144

    float* out = (float*)d_out;
    float* content = out;
    // attn goes to d_out if there is room for both outputs, else to scratch
    float* attn;
    float* scratch;
    cudaGetSymbolAddress((void**)&scratch, g_attn_scratch);
    if ((long)out_size >= (long)nrows * (DV + NS)) {
        attn = out + (long)nrows * DV;
    } else {
        attn = scratch;
    }

    const int rows_per_warp = 4;
    const int rows_per_block = 8 * rows_per_warp;  // 32
    const int grid1 = (nrows + rows_per_block - 1) / rows_per_block;
    proj_softmax_kernel<<<grid1, 256>>>(query, W1, b1, W2, b2, keys,
                                        attn, nrows, rows_per_warp);

    dim3 g2(DV / BN, (nrows + BM - 1) / BM);
    content_gemm_kernel<<<g2, 256>>>(attn, values, content, nrows);
}

// round 3
// speedup vs baseline: 5.8295x; 5.8295x over previous
#include <cuda_runtime.h>
#include <cuda_fp16.h>
#include <math.h>
#include <stdint.h>

#define DQ 14
#define HID 32
#define DK 8
#define NS 240
#define DV 256
#define NTHREADS 512
#define TILE_M 128
#define NKSTEP 15          // 240 / 16
#define AK 264             // A smem row stride in halves (528 B, conflict-free)
#define BN 264             // B smem row stride in halves

// ---- smem layout (bytes) ----
#define SO_W1P    0            // float[32*15]
#define SO_B1     1920         // float[32]
#define SO_W2T    2048         // float[32*9]
#define SO_B2     3200         // float[8]
#define SO_KEYS   3232         // float[256*9] (zero padded)
#define SO_H      12448        // float[16][32]
#define SO_A      14496        // half[128][AK]  = 67584 B
#define SO_B      82080        // half[240][BN]  = 126720 B
#define SMEM_TOTAL 208800

#define BETA 2.0f

__device__ float g_attn_scratch[262144 * NS];

// ---------------------------------------------------------------------------
__device__ __forceinline__ uint32_t smem_u32(const void* p) {
    uint32_t a;
    asm("{ .reg .u64 t; cvta.to.shared.u64 t, %1; cvt.u32.u64 %0, t; }" : "=r"(a) : "l"(p));
    return a;
}
__device__ __forceinline__ void ldsm_x4(uint32_t& r0, uint32_t& r1, uint32_t& r2, uint32_t& r3,
                                        uint32_t addr) {
    asm volatile("ldmatrix.sync.aligned.m8n8.x4.shared.b16 {%0,%1,%2,%3}, [%4];"
                 : "=r"(r0), "=r"(r1), "=r"(r2), "=r"(r3) : "r"(addr));
}
__device__ __forceinline__ void ldsm_x2t(uint32_t& r0, uint32_t& r1, uint32_t addr) {
    asm volatile("ldmatrix.sync.aligned.m8n8.x2.trans.shared.b16 {%0,%1}, [%2];"
                 : "=r"(r0), "=r"(r1) : "r"(addr));
}
__device__ __forceinline__ void mma16816(float* d, uint32_t a0, uint32_t a1, uint32_t a2,
                                         uint32_t a3, uint32_t b0, uint32_t b1) {
    asm volatile(
        "mma.sync.aligned.m16n8k16.row.col.f32.f16.f16.f32 "
        "{%0,%1,%2,%3}, {%4,%5,%6,%7}, {%8,%9}, {%0,%1,%2,%3};"
        : "+f"(d[0]), "+f"(d[1]), "+f"(d[2]), "+f"(d[3])
        : "r"(a0), "r"(a1), "r"(a2), "r"(a3), "r"(b0), "r"(b1));
}
__device__ __forceinline__ void sts_u16(uint32_t addr, unsigned short v) {
    asm volatile("st.shared.u16 [%0], %1;" :: "r"(addr), "h"(v) : "memory");
}
__device__ __forceinline__ void sts_u32(uint32_t addr, uint32_t v) {
    asm volatile("st.shared.u32 [%0], %1;" :: "r"(addr), "r"(v) : "memory");
}

// ---------------------------------------------------------------------------
__global__ __launch_bounds__(NTHREADS, 1) void fused_kernel(
    const float* __restrict__ query,
    const float* __restrict__ W1, const float* __restrict__ b1,
    const float* __restrict__ W2, const float* __restrict__ b2,
    const float* __restrict__ values,
    const float* __restrict__ keys,
    float* __restrict__ content,
    float* __restrict__ attn_out,
    int nrows, int ntiles)
{
    extern __shared__ char smem[];
    float* W1p_s  = (float*)(smem + SO_W1P);
    float* b1_s   = (float*)(smem + SO_B1);
    float* W2t_s  = (float*)(smem + SO_W2T);
    float* b2_s   = (float*)(smem + SO_B2);
    float* keys_s = (float*)(smem + SO_KEYS);
    float* h_s    = (float*)(smem + SO_H);

    const uint32_t smem_base = smem_u32(smem);
    const uint32_t a_base = smem_base + SO_A;
    const uint32_t b_base = smem_base + SO_B;

    const int tid  = threadIdx.x;
    const int warp = tid >> 5;
    const int lane = tid & 31;

    // ---- one-time setup: weights/keys + B tile (values -> fp16 smem) ----
    for (int i = tid; i < HID * DQ; i += NTHREADS)
        W1p_s[(i / DQ) * 15 + (i % DQ)] = W1[i];
    for (int i = tid; i < HID; i += NTHREADS) b1_s[i] = b1[i];
    for (int i = tid; i < DK * HID; i += NTHREADS) {
        int r = i / HID, c = i % HID;
        W2t_s[c * 9 + r] = W2[i];
    }
    for (int i = tid; i < DK; i += NTHREADS) b2_s[i] = b2[i];
    for (int i = tid; i < 256 * 9; i += NTHREADS) keys_s[i] = 0.f;
    __syncthreads();
    for (int i = tid; i < NS * DK; i += NTHREADS)
        keys_s[(i / DK) * 9 + (i % DK)] = keys[i];

    // B_s[k][n] fp16, row stride BN halves; values is [240][256] fp32
    for (int i = tid; i < NS * (DV / 2); i += NTHREADS) {
        const int k  = i / (DV / 2);
        const int np = i % (DV / 2);
        const float2 v = __ldg((const float2*)(values + k * DV + 2 * np));
        const __half2 h2 = __floats2half2_rn(v.x, v.y);
        sts_u32(b_base + (k * BN + 2 * np) * 2, *(const uint32_t*)&h2);
    }
    __syncthreads();

    for (int tile = blockIdx.x; tile < ntiles; tile += gridDim.x) {
        const long row0 = (long)tile * TILE_M;

        // ================= Phase A: projection + softmax ===================
        for (int rr = 0; rr < 8; rr++) {
            const int  mloc = warp * 8 + rr;
            const long row  = row0 + mloc;
            if (row < nrows) {
                const float2* xp = (const float2*)(query + row * DQ);
                float xr[DQ];
                #pragma unroll
                for (int d = 0; d < 7; d++) {
                    float2 v = __ldg(&xp[d]);
                    xr[2 * d] = v.x; xr[2 * d + 1] = v.y;
                }
                // hidden: lane = hidden unit, exact GELU
                float hj = b1_s[lane];
                #pragma unroll
                for (int d = 0; d < DQ; d++) hj = fmaf(W1p_s[lane * 15 + d], xr[d], hj);
                hj = 0.5f * hj * (1.0f + erff(hj * 0.7071067811865476f));
                h_s[warp * HID + lane] = hj;
                __syncwarp();

                // q8: lane computes component (lane & 7), 4x redundant
                const int ci = lane & 7;
                float q = b2_s[ci];
                #pragma unroll
                for (int j = 0; j < HID; j++)
                    q = fmaf(W2t_s[j * 9 + ci], h_s[warp * HID + j], q);
                __syncwarp();
                float ss = q * q;
                ss += __shfl_xor_sync(0xffffffffu, ss, 1);
                ss += __shfl_xor_sync(0xffffffffu, ss, 2);
                ss += __shfl_xor_sync(0xffffffffu, ss, 4);
                const float inv = 1.0f / fmaxf(sqrtf(ss), 1e-12f);
                const float qn = q * inv;
                float q8[DK];
                #pragma unroll
                for (int i = 0; i < DK; i++) q8[i] = __shfl_sync(0xffffffffu, qn, i);

                // sim over 240 keys; fixed-shift softmax (sim <= 1 always)
                float e[8];
                float ssum = 0.f;
                #pragma unroll
                for (int t = 0; t < 8; t++) {
                    const int k = lane + 32 * t;
                    float s = 0.f;
                    #pragma unroll
                    for (int i = 0; i < DK; i++)
                        s = fmaf(q8[i], keys_s[k * 9 + i], s);
                    float ev = __expf(BETA * (s - 1.0f));
                    if (k >= NS) ev = 0.f;
                    e[t] = ev;
                    ssum += ev;
                }
                #pragma unroll
                for (int o = 16; o > 0; o >>= 1)
                    ssum += __shfl_xor_sync(0xffffffffu, ssum, o);
                const float invs = 1.0f / ssum;

                float* arow = attn_out + row * NS;
                const uint32_t abase_row = a_base + mloc * (AK * 2);
                #pragma unroll
                for (int t = 0; t < 8; t++) {
                    const int k = lane + 32 * t;
                    if (k < NS) {
                        const float a = e[t] * invs;
                        arow[k] = a;
                        sts_u16(abase_row + k * 2,
                                __half_as_ushort(__float2half_rn(a)));
                    }
                }
            }
        }
        __syncthreads();

        // ========== Phase B: content = A(attn,fp16) @ B(values,fp16) =======
        {
            const int mt  = warp & 7;          // m-tile (16 rows)
            const int nh  = warp >> 3;         // n half (128 cols)
            const int m0  = mt * 16;
            const int n0b = nh * 128;

            float acc[16][4];
            #pragma unroll
            for (int t = 0; t < 16; t++)
                #pragma unroll
                for (int j = 0; j < 4; j++) acc[t][j] = 0.f;

            // ldmatrix source addresses (lane-dependent parts)
            const uint32_t a_lane = a_base
                + ((m0 + (lane & 15)) * AK + (lane >> 4) * 8) * 2;
            const uint32_t b_lane = b_base + ((lane & 15) * BN + n0b) * 2;

            #pragma unroll
            for (int ks = 0; ks < NKSTEP; ks++) {
                uint32_t a0, a1, a2, a3;
                ldsm_x4(a0, a1, a2, a3, a_lane + ks * 32);   // +16 halves
                const uint32_t bk = b_lane + ks * (16 * BN * 2);
                #pragma unroll
                for (int t = 0; t < 16; t++) {
                    uint32_t b0, b1;
                    ldsm_x2t(b0, b1, bk + t * 16);           // +8 halves
                    mma16816(acc[t], a0, a1, a2, a3, b0, b1);
                }
            }

            // epilogue: direct stores (all rows valid: nrows % 128 == 0 here,
            // still guarded for safety)
            const long r0 = row0 + m0 + (lane >> 2);
            const int  cofs = (lane & 3) * 2;
            #pragma unroll
            for (int t = 0; t < 16; t++) {
                const int col = n0b + t * 8 + cofs;
                if (r0 < nrows)
                    *(float2*)(content + r0 * DV + col) = make_float2(acc[t][0], acc[t][1]);
                if (r0 + 8 < nrows)
                    *(float2*)(content + (r0 + 8) * DV + col) = make_float2(acc[t][2], acc[t][3]);
            }
        }
        __syncthreads();   // A_s fully consumed before next tile overwrites
    }
}

// ---------------------------------------------------------------------------
extern "C" void kernel_launch(void* const* d_in, const int* in_sizes, int n_in,
                              void* d_out, int out_size)
{
    const float* query  = (const float*)d_in[0];
    const float* W1     = (const float*)d_in[1];
    const float* b1     = (const float*)d_in[2];
    const float* W2     = (const float*)d_in[3];
    const float* b2     = (const float*)d_in[4];
    const float* values = (const float*)d_in[5];
    const float* keys   = (const float*)d_in[6];

    const int nrows  = in_sizes[0] / DQ;   // 262144
    const int ntiles = (nrows + TILE_M - 1) / TILE_M;

    float* out = (float*)d_out;
    float* content = out;
    float* attn;
    float* scratch;
    cudaGetSymbolAddress((void**)&scratch, g_attn_scratch);
    if ((long)out_size >= (long)nrows * (DV + NS)) {
        attn = out + (long)nrows * DV;
    } else {
        attn = scratch;
    }

    cudaFuncSetAttribute(fused_kernel, cudaFuncAttributeMaxDynamicSharedMemorySize,
                         SMEM_TOTAL);

    fused_kernel<<<152, NTHREADS, SMEM_TOTAL>>>(
        query, W1, b1, W2, b2, values, keys, content, attn, nrows, ntiles);
}

// round 4
// speedup vs baseline: 5.9519x; 1.0210x over previous
#include <cuda_runtime.h>
#include <cuda_fp16.h>
#include <math.h>
#include <stdint.h>

#define DQ 14
#define HID 32
#define DK 8
#define NS 240
#define DV 256
#define NTHREADS 512
#define TILE_M 128
#define NKSTEP 15          // 240 / 16
#define AK 248             // A smem row stride in halves (496 B)
#define BK 248             // B smem row stride in halves (496 B)

// ---- smem layout (bytes) ----
#define SO_W1P    0            // float[32*15]
#define SO_B1     1920         // float[32]
#define SO_W2T    2048         // float[32*9]
#define SO_B2     3200         // float[8]
#define SO_KEYS   3232         // float[256*9] (zero padded)
#define SO_H      12448        // float[16][32]
#define SO_A      14496        // half[128][AK] = 63488 B
#define SO_B      77984        // half[256][BK] = 126976 B (values, n-major)
#define SMEM_TOTAL 204960

#define BETA 2.0f

__device__ float g_attn_scratch[262144 * NS];

// ---------------------------------------------------------------------------
__device__ __forceinline__ uint32_t smem_u32(const void* p) {
    uint32_t a;
    asm("{ .reg .u64 t; cvta.to.shared.u64 t, %1; cvt.u32.u64 %0, t; }" : "=r"(a) : "l"(p));
    return a;
}
__device__ __forceinline__ void ldsm_x4(uint32_t& r0, uint32_t& r1, uint32_t& r2, uint32_t& r3,
                                        uint32_t addr) {
    asm volatile("ldmatrix.sync.aligned.m8n8.x4.shared.b16 {%0,%1,%2,%3}, [%4];"
                 : "=r"(r0), "=r"(r1), "=r"(r2), "=r"(r3) : "r"(addr));
}
__device__ __forceinline__ void mma16816(float* d, uint32_t a0, uint32_t a1, uint32_t a2,
                                         uint32_t a3, uint32_t b0, uint32_t b1) {
    asm volatile(
        "mma.sync.aligned.m16n8k16.row.col.f32.f16.f16.f32 "
        "{%0,%1,%2,%3}, {%4,%5,%6,%7}, {%8,%9}, {%0,%1,%2,%3};"
        : "+f"(d[0]), "+f"(d[1]), "+f"(d[2]), "+f"(d[3])
        : "r"(a0), "r"(a1), "r"(a2), "r"(a3), "r"(b0), "r"(b1));
}
__device__ __forceinline__ void sts_u16(uint32_t addr, unsigned short v) {
    asm volatile("st.shared.u16 [%0], %1;" :: "r"(addr), "h"(v) : "memory");
}

// ---------------------------------------------------------------------------
__global__ __launch_bounds__(NTHREADS, 1) void fused_kernel(
    const float* __restrict__ query,
    const float* __restrict__ W1, const float* __restrict__ b1,
    const float* __restrict__ W2, const float* __restrict__ b2,
    const float* __restrict__ values,
    const float* __restrict__ keys,
    float* __restrict__ content,
    float* __restrict__ attn_out,
    int nrows, int ntiles)
{
    extern __shared__ char smem[];
    float* W1p_s  = (float*)(smem + SO_W1P);
    float* b1_s   = (float*)(smem + SO_B1);
    float* W2t_s  = (float*)(smem + SO_W2T);
    float* b2_s   = (float*)(smem + SO_B2);
    float* keys_s = (float*)(smem + SO_KEYS);
    float* h_s    = (float*)(smem + SO_H);

    const uint32_t smem_base = smem_u32(smem);
    const uint32_t a_base = smem_base + SO_A;
    const uint32_t b_base = smem_base + SO_B;

    const int tid  = threadIdx.x;
    const int warp = tid >> 5;
    const int lane = tid & 31;

    // ---- one-time setup: weights/keys ----
    for (int i = tid; i < HID * DQ; i += NTHREADS)
        W1p_s[(i / DQ) * 15 + (i % DQ)] = W1[i];
    for (int i = tid; i < HID; i += NTHREADS) b1_s[i] = b1[i];
    for (int i = tid; i < DK * HID; i += NTHREADS) {
        int r = i / HID, c = i % HID;
        W2t_s[c * 9 + r] = W2[i];
    }
    for (int i = tid; i < DK; i += NTHREADS) b2_s[i] = b2[i];
    for (int i = tid; i < 256 * 9; i += NTHREADS) keys_s[i] = 0.f;
    __syncthreads();
    for (int i = tid; i < NS * DK; i += NTHREADS)
        keys_s[(i / DK) * 9 + (i % DK)] = keys[i];

    // Bn[n][k] fp16 (n-major transpose of values[k][n]); one-time
    for (int i = tid; i < NS * (DV / 2); i += NTHREADS) {
        const int k  = i / (DV / 2);
        const int np = i % (DV / 2);
        const float2 v = __ldg((const float2*)(values + k * DV + 2 * np));
        sts_u16(b_base + ((2 * np)     * BK + k) * 2,
                __half_as_ushort(__float2half_rn(v.x)));
        sts_u16(b_base + ((2 * np + 1) * BK + k) * 2,
                __half_as_ushort(__float2half_rn(v.y)));
    }
    __syncthreads();

    for (int tile = blockIdx.x; tile < ntiles; tile += gridDim.x) {
        const long row0 = (long)tile * TILE_M;

        // ================= Phase A: projection + softmax ===================
        for (int rr = 0; rr < 8; rr++) {
            const int  mloc = warp * 8 + rr;
            const long row  = row0 + mloc;
            if (row < nrows) {
                const float2* xp = (const float2*)(query + row * DQ);
                float xr[DQ];
                #pragma unroll
                for (int d = 0; d < 7; d++) {
                    float2 v = __ldg(&xp[d]);
                    xr[2 * d] = v.x; xr[2 * d + 1] = v.y;
                }
                // hidden: lane = hidden unit, exact GELU
                float hj = b1_s[lane];
                #pragma unroll
                for (int d = 0; d < DQ; d++) hj = fmaf(W1p_s[lane * 15 + d], xr[d], hj);
                hj = 0.5f * hj * (1.0f + erff(hj * 0.7071067811865476f));
                h_s[warp * HID + lane] = hj;
                __syncwarp();

                // q8: lane computes component (lane & 7), 4x redundant
                const int ci = lane & 7;
                float q = b2_s[ci];
                #pragma unroll
                for (int j = 0; j < HID; j++)
                    q = fmaf(W2t_s[j * 9 + ci], h_s[warp * HID + j], q);
                __syncwarp();
                float ss = q * q;
                ss += __shfl_xor_sync(0xffffffffu, ss, 1);
                ss += __shfl_xor_sync(0xffffffffu, ss, 2);
                ss += __shfl_xor_sync(0xffffffffu, ss, 4);
                const float inv = 1.0f / fmaxf(sqrtf(ss), 1e-12f);
                const float qn = q * inv;
                float q8[DK];
                #pragma unroll
                for (int i = 0; i < DK; i++) q8[i] = __shfl_sync(0xffffffffu, qn, i);

                // sim over 240 keys; fixed-shift softmax (sim <= 1 always)
                float e[8];
                float ssum = 0.f;
                #pragma unroll
                for (int t = 0; t < 8; t++) {
                    const int k = lane + 32 * t;
                    float s = 0.f;
                    #pragma unroll
                    for (int i = 0; i < DK; i++)
                        s = fmaf(q8[i], keys_s[k * 9 + i], s);
                    float ev = __expf(BETA * (s - 1.0f));
                    if (k >= NS) ev = 0.f;
                    e[t] = ev;
                    ssum += ev;
                }
                #pragma unroll
                for (int o = 16; o > 0; o >>= 1)
                    ssum += __shfl_xor_sync(0xffffffffu, ssum, o);
                const float invs = 1.0f / ssum;

                float* arow = attn_out + row * NS;
                const uint32_t abase_row = a_base + mloc * (AK * 2);
                #pragma unroll
                for (int t = 0; t < 8; t++) {
                    const int k = lane + 32 * t;
                    if (k < NS) {
                        const float a = e[t] * invs;
                        arow[k] = a;
                        sts_u16(abase_row + k * 2,
                                __half_as_ushort(__float2half_rn(a)));
                    }
                }
            }
        }
        __syncthreads();

        // ========== Phase B: content = A(attn) @ Bn^T, 32m x 64n warp tiles =
        {
            const int m0 = (warp & 3) * 32;
            const int n0 = (warp >> 2) * 64;

            float acc[2][8][4];
            #pragma unroll
            for (int i = 0; i < 2; i++)
                #pragma unroll
                for (int t = 0; t < 8; t++)
                    #pragma unroll
                    for (int j = 0; j < 4; j++) acc[i][t][j] = 0.f;

            // A x4 address: lanes 0-15 rows m..m+15 @k0; lanes 16-31 same rows @k0+8
            const uint32_t a_lane0 = a_base
                + ((m0 + (lane & 15)) * AK + (lane >> 4) * 8) * 2;
            const uint32_t a_lane1 = a_lane0 + 16 * AK * 2;
            // B x4 address: mats (n0..7,k0),(n0..7,k0+8),(n8..15,k0),(n8..15,k0+8)
            const uint32_t b_lane = b_base
                + ((n0 + ((lane >> 4) << 3) + (lane & 7)) * BK
                   + (((lane >> 3) & 1) * 8)) * 2;

            #pragma unroll
            for (int ks = 0; ks < NKSTEP; ks++) {
                uint32_t a0[4], a1[4];
                ldsm_x4(a0[0], a0[1], a0[2], a0[3], a_lane0 + ks * 32);
                ldsm_x4(a1[0], a1[1], a1[2], a1[3], a_lane1 + ks * 32);
                #pragma unroll
                for (int np = 0; np < 4; np++) {
                    uint32_t b0, b1, b2, b3;   // (b0,b1)=n-tile 2np, (b2,b3)=2np+1
                    ldsm_x4(b0, b1, b2, b3, b_lane + (np * 16 * BK + ks * 16) * 2);
                    mma16816(acc[0][2 * np],     a0[0], a0[1], a0[2], a0[3], b0, b1);
                    mma16816(acc[0][2 * np + 1], a0[0], a0[1], a0[2], a0[3], b2, b3);
                    mma16816(acc[1][2 * np],     a1[0], a1[1], a1[2], a1[3], b0, b1);
                    mma16816(acc[1][2 * np + 1], a1[0], a1[1], a1[2], a1[3], b2, b3);
                }
            }

            // epilogue
            #pragma unroll
            for (int i = 0; i < 2; i++) {
                const long r0 = row0 + m0 + i * 16 + (lane >> 2);
                const int cofs = (lane & 3) * 2;
                #pragma unroll
                for (int t = 0; t < 8; t++) {
                    const int col = n0 + t * 8 + cofs;
                    if (r0 < nrows)
                        *(float2*)(content + r0 * DV + col) =
                            make_float2(acc[i][t][0], acc[i][t][1]);
                    if (r0 + 8 < nrows)
                        *(float2*)(content + (r0 + 8) * DV + col) =
                            make_float2(acc[i][t][2], acc[i][t][3]);
                }
            }
        }
        __syncthreads();   // A_s fully consumed before next tile overwrites
    }
}

// ---------------------------------------------------------------------------
extern "C" void kernel_launch(void* const* d_in, const int* in_sizes, int n_in,
                              void* d_out, int out_size)
{
    const float* query  = (const float*)d_in[0];
    const float* W1     = (const float*)d_in[1];
    const float* b1     = (const float*)d_in[2];
    const float* W2     = (const float*)d_in[3];
    const float* b2     = (const float*)d_in[4];
    const float* values = (const float*)d_in[5];
    const float* keys   = (const float*)d_in[6];

    const int nrows  = in_sizes[0] / DQ;   // 262144
    const int ntiles = (nrows + TILE_M - 1) / TILE_M;

    float* out = (float*)d_out;
    float* content = out;
    float* attn;
    float* scratch;
    cudaGetSymbolAddress((void**)&scratch, g_attn_scratch);
    if ((long)out_size >= (long)nrows * (DV + NS)) {
        attn = out + (long)nrows * DV;
    } else {
        attn = scratch;
    }

    cudaFuncSetAttribute(fused_kernel, cudaFuncAttributeMaxDynamicSharedMemorySize,
                         SMEM_TOTAL);

    fused_kernel<<<152, NTHREADS, SMEM_TOTAL>>>(
        query, W1, b1, W2, b2, values, keys, content, attn, nrows, ntiles);
}

// round 6
// speedup vs baseline: 6.1984x; 1.0414x over previous
#include <cuda_runtime.h>
#include <cuda_fp16.h>
#include <math.h>
#include <stdint.h>

#define DQ 14
#define HID 32
#define DK 8
#define NS 240
#define DV 256
#define NTHREADS 1024
#define TILE_M 128
#define NKSTEP 15          // 240 / 16
#define AK 248             // A smem row stride in halves (496 B)
#define BK 248             // B smem row stride in halves (496 B)

// ---- smem layout (bytes) ----
#define SO_W1P    0            // float[32*15]
#define SO_B1     1920         // float[32]
#define SO_W2T    2048         // float[32*9]
#define SO_B2     3200         // float[8]
#define SO_KEYS   3232         // float[256*9] (zero padded)
#define SO_H      12448        // float[32][32]
#define SO_A      16544        // half[128][AK] = 63488 B
#define SO_B      80032        // half[256][BK] = 126976 B (values, n-major)
#define SMEM_TOTAL 207008

#define BETA 2.0f

__device__ float g_attn_scratch[262144 * NS];

// ---------------------------------------------------------------------------
__device__ __forceinline__ uint32_t smem_u32(const void* p) {
    uint32_t a;
    asm("{ .reg .u64 t; cvta.to.shared.u64 t, %1; cvt.u32.u64 %0, t; }" : "=r"(a) : "l"(p));
    return a;
}
__device__ __forceinline__ void ldsm_x4(uint32_t& r0, uint32_t& r1, uint32_t& r2, uint32_t& r3,
                                        uint32_t addr) {
    asm volatile("ldmatrix.sync.aligned.m8n8.x4.shared.b16 {%0,%1,%2,%3}, [%4];"
                 : "=r"(r0), "=r"(r1), "=r"(r2), "=r"(r3) : "r"(addr));
}
__device__ __forceinline__ void mma16816(float* d, uint32_t a0, uint32_t a1, uint32_t a2,
                                         uint32_t a3, uint32_t b0, uint32_t b1) {
    asm volatile(
        "mma.sync.aligned.m16n8k16.row.col.f32.f16.f16.f32 "
        "{%0,%1,%2,%3}, {%4,%5,%6,%7}, {%8,%9}, {%0,%1,%2,%3};"
        : "+f"(d[0]), "+f"(d[1]), "+f"(d[2]), "+f"(d[3])
        : "r"(a0), "r"(a1), "r"(a2), "r"(a3), "r"(b0), "r"(b1));
}
__device__ __forceinline__ void sts_u16(uint32_t addr, unsigned short v) {
    asm volatile("st.shared.u16 [%0], %1;" :: "r"(addr), "h"(v) : "memory");
}

// ---------------------------------------------------------------------------
__global__ __launch_bounds__(NTHREADS, 1) void fused_kernel(
    const float* __restrict__ query,
    const float* __restrict__ W1, const float* __restrict__ b1,
    const float* __restrict__ W2, const float* __restrict__ b2,
    const float* __restrict__ values,
    const float* __restrict__ keys,
    float* __restrict__ content,
    float* __restrict__ attn_out,
    int nrows, int ntiles)
{
    extern __shared__ char smem[];
    float* W1p_s  = (float*)(smem + SO_W1P);
    float* b1_s   = (float*)(smem + SO_B1);
    float* W2t_s  = (float*)(smem + SO_W2T);
    float* b2_s   = (float*)(smem + SO_B2);
    float* keys_s = (float*)(smem + SO_KEYS);
    float* h_s    = (float*)(smem + SO_H);

    const uint32_t smem_base = smem_u32(smem);
    const uint32_t a_base = smem_base + SO_A;
    const uint32_t b_base = smem_base + SO_B;

    const int tid  = threadIdx.x;
    const int warp = tid >> 5;
    const int lane = tid & 31;

    // ---- one-time setup: weights/keys ----
    for (int i = tid; i < HID * DQ; i += NTHREADS)
        W1p_s[(i / DQ) * 15 + (i % DQ)] = W1[i];
    for (int i = tid; i < HID; i += NTHREADS) b1_s[i] = b1[i];
    for (int i = tid; i < DK * HID; i += NTHREADS) {
        int r = i / HID, c = i % HID;
        W2t_s[c * 9 + r] = W2[i];
    }
    for (int i = tid; i < DK; i += NTHREADS) b2_s[i] = b2[i];
    for (int i = tid; i < 256 * 9; i += NTHREADS) keys_s[i] = 0.f;
    __syncthreads();
    for (int i = tid; i < NS * DK; i += NTHREADS)
        keys_s[(i / DK) * 9 + (i % DK)] = keys[i];

    // Bn[n][k] fp16 (n-major transpose of values[k][n]); one-time
    for (int i = tid; i < NS * (DV / 2); i += NTHREADS) {
        const int k  = i / (DV / 2);
        const int np = i % (DV / 2);
        const float2 v = __ldg((const float2*)(values + k * DV + 2 * np));
        sts_u16(b_base + ((2 * np)     * BK + k) * 2,
                __half_as_ushort(__float2half_rn(v.x)));
        sts_u16(b_base + ((2 * np + 1) * BK + k) * 2,
                __half_as_ushort(__float2half_rn(v.y)));
    }
    __syncthreads();

    for (int tile = blockIdx.x; tile < ntiles; tile += gridDim.x) {
        const long row0 = (long)tile * TILE_M;

        // ================= Phase A: projection + softmax ===================
        for (int rr = 0; rr < 4; rr++) {
            const int  mloc = warp * 4 + rr;
            const long row  = row0 + mloc;
            if (row < nrows) {
                const float2* xp = (const float2*)(query + row * DQ);
                float xr[DQ];
                #pragma unroll
                for (int d = 0; d < 7; d++) {
                    float2 v = __ldg(&xp[d]);
                    xr[2 * d] = v.x; xr[2 * d + 1] = v.y;
                }
                // hidden: lane = hidden unit, exact GELU
                float hj = b1_s[lane];
                #pragma unroll
                for (int d = 0; d < DQ; d++) hj = fmaf(W1p_s[lane * 15 + d], xr[d], hj);
                hj = 0.5f * hj * (1.0f + erff(hj * 0.7071067811865476f));
                h_s[warp * HID + lane] = hj;
                __syncwarp();

                // q8: lane computes component (lane & 7), 4x redundant
                const int ci = lane & 7;
                float q = b2_s[ci];
                #pragma unroll
                for (int j = 0; j < HID; j++)
                    q = fmaf(W2t_s[j * 9 + ci], h_s[warp * HID + j], q);
                __syncwarp();
                float ss = q * q;
                ss += __shfl_xor_sync(0xffffffffu, ss, 1);
                ss += __shfl_xor_sync(0xffffffffu, ss, 2);
                ss += __shfl_xor_sync(0xffffffffu, ss, 4);
                const float inv = 1.0f / fmaxf(sqrtf(ss), 1e-12f);
                const float qn = q * inv;
                float q8[DK];
                #pragma unroll
                for (int i = 0; i < DK; i++) q8[i] = __shfl_sync(0xffffffffu, qn, i);

                // sim over 240 keys; fixed-shift softmax (sim <= 1 always)
                float e[8];
                float ssum = 0.f;
                #pragma unroll
                for (int t = 0; t < 8; t++) {
                    const int k = lane + 32 * t;
                    float s = 0.f;
                    #pragma unroll
                    for (int i = 0; i < DK; i++)
                        s = fmaf(q8[i], keys_s[k * 9 + i], s);
                    float ev = __expf(BETA * (s - 1.0f));
                    if (k >= NS) ev = 0.f;
                    e[t] = ev;
                    ssum += ev;
                }
                #pragma unroll
                for (int o = 16; o > 0; o >>= 1)
                    ssum += __shfl_xor_sync(0xffffffffu, ssum, o);
                const float invs = 1.0f / ssum;

                float* arow = attn_out + row * NS;
                const uint32_t abase_row = a_base + mloc * (AK * 2);
                #pragma unroll
                for (int t = 0; t < 8; t++) {
                    const int k = lane + 32 * t;
                    if (k < NS) {
                        const float a = e[t] * invs;
                        arow[k] = a;
                        sts_u16(abase_row + k * 2,
                                __half_as_ushort(__float2half_rn(a)));
                    }
                }
            }
        }
        __syncthreads();

        // ===== Phase B: content = A(attn) @ Bn^T, 32m x 32n warp tiles =====
        {
            const int m0 = (warp & 3) * 32;
            const int n0 = (warp >> 2) * 32;

            float acc[2][4][4];
            #pragma unroll
            for (int i = 0; i < 2; i++)
                #pragma unroll
                for (int t = 0; t < 4; t++)
                    #pragma unroll
                    for (int j = 0; j < 4; j++) acc[i][t][j] = 0.f;

            // A x4: lanes 0-15 rows m..m+15 @k0; lanes 16-31 same rows @k0+8
            const uint32_t a_lane0 = a_base
                + ((m0 + (lane & 15)) * AK + (lane >> 4) * 8) * 2;
            const uint32_t a_lane1 = a_lane0 + 16 * AK * 2;
            // B x4: mats (n0..7,k0),(n0..7,k0+8),(n8..15,k0),(n8..15,k0+8)
            const uint32_t b_lane = b_base
                + ((n0 + ((lane >> 4) << 3) + (lane & 7)) * BK
                   + (((lane >> 3) & 1) * 8)) * 2;

            #pragma unroll
            for (int ks = 0; ks < NKSTEP; ks++) {
                uint32_t a0[4], a1[4];
                ldsm_x4(a0[0], a0[1], a0[2], a0[3], a_lane0 + ks * 32);
                ldsm_x4(a1[0], a1[1], a1[2], a1[3], a_lane1 + ks * 32);
                #pragma unroll
                for (int np = 0; np < 2; np++) {
                    uint32_t b0, b1, b2, b3;
                    ldsm_x4(b0, b1, b2, b3, b_lane + (np * 16 * BK + ks * 16) * 2);
                    mma16816(acc[0][2 * np],     a0[0], a0[1], a0[2], a0[3], b0, b1);
                    mma16816(acc[0][2 * np + 1], a0[0], a0[1], a0[2], a0[3], b2, b3);
                    mma16816(acc[1][2 * np],     a1[0], a1[1], a1[2], a1[3], b0, b1);
                    mma16816(acc[1][2 * np + 1], a1[0], a1[1], a1[2], a1[3], b2, b3);
                }
            }

            // epilogue
            #pragma unroll
            for (int i = 0; i < 2; i++) {
                const long r0 = row0 + m0 + i * 16 + (lane >> 2);
                const int cofs = (lane & 3) * 2;
                #pragma unroll
                for (int t = 0; t < 4; t++) {
                    const int col = n0 + t * 8 + cofs;
                    if (r0 < nrows)
                        *(float2*)(content + r0 * DV + col) =
                            make_float2(acc[i][t][0], acc[i][t][1]);
                    if (r0 + 8 < nrows)
                        *(float2*)(content + (r0 + 8) * DV + col) =
                            make_float2(acc[i][t][2], acc[i][t][3]);
                }
            }
        }
        __syncthreads();   // A_s fully consumed before next tile overwrites
    }
}

// ---------------------------------------------------------------------------
extern "C" void kernel_launch(void* const* d_in, const int* in_sizes, int n_in,
                              void* d_out, int out_size)
{
    const float* query  = (const float*)d_in[0];
    const float* W1     = (const float*)d_in[1];
    const float* b1     = (const float*)d_in[2];
    const float* W2     = (const float*)d_in[3];
    const float* b2     = (const float*)d_in[4];
    const float* values = (const float*)d_in[5];
    const float* keys   = (const float*)d_in[6];

    const int nrows  = in_sizes[0] / DQ;   // 262144
    const int ntiles = (nrows + TILE_M - 1) / TILE_M;

    float* out = (float*)d_out;
    float* content = out;
    float* attn;
    float* scratch;
    cudaGetSymbolAddress((void**)&scratch, g_attn_scratch);
    if ((long)out_size >= (long)nrows * (DV + NS)) {
        attn = out + (long)nrows * DV;
    } else {
        attn = scratch;
    }

    cudaFuncSetAttribute(fused_kernel, cudaFuncAttributeMaxDynamicSharedMemorySize,
                         SMEM_TOTAL);

    fused_kernel<<<152, NTHREADS, SMEM_TOTAL>>>(
        query, W1, b1, W2, b2, values, keys, content, attn, nrows, ntiles);
}

// round 7
// speedup vs baseline: 7.0575x; 1.1386x over previous
#include <cuda_runtime.h>
#include <cuda_fp16.h>
#include <math.h>
#include <stdint.h>

#define DQ 14
#define HID 32
#define DK 8
#define NS 240
#define DV 256
#define NTHREADS 1024
#define TILE_M 128
#define NKSTEP 15          // 240 / 16
#define AK 248             // A smem row stride in halves (496 B)
#define BKS 248            // B smem row stride in halves (496 B)

// ---- smem layout (bytes) ----
#define SO_W1P    0            // float[32][20] (pad, 14 used)
#define SO_B1     2560         // float[32]
#define SO_W2R    2688         // float[8][36]  (pad, 32 used)
#define SO_B2     3840         // float[8]
#define SO_KEYS   3872         // float[240][12] (pad, 8 used)
#define SO_H      15392        // float[32][32]
#define SO_RS     19488        // float[128] row sums
#define SO_A      20000        // half[128][AK] = 63488 B (unnormalized e)
#define SO_B      83488        // half[256][BKS] = 126976 B (values, n-major)
#define SMEM_TOTAL 210464

#define BETA 2.0f

__device__ float g_attn_scratch[262144 * NS];

// ---------------------------------------------------------------------------
__device__ __forceinline__ uint32_t smem_u32(const void* p) {
    uint32_t a;
    asm("{ .reg .u64 t; cvta.to.shared.u64 t, %1; cvt.u32.u64 %0, t; }" : "=r"(a) : "l"(p));
    return a;
}
__device__ __forceinline__ void ldsm_x4(uint32_t& r0, uint32_t& r1, uint32_t& r2, uint32_t& r3,
                                        uint32_t addr) {
    asm volatile("ldmatrix.sync.aligned.m8n8.x4.shared.b16 {%0,%1,%2,%3}, [%4];"
                 : "=r"(r0), "=r"(r1), "=r"(r2), "=r"(r3) : "r"(addr));
}
__device__ __forceinline__ void mma16816(float* d, uint32_t a0, uint32_t a1, uint32_t a2,
                                         uint32_t a3, uint32_t b0, uint32_t b1) {
    asm volatile(
        "mma.sync.aligned.m16n8k16.row.col.f32.f16.f16.f32 "
        "{%0,%1,%2,%3}, {%4,%5,%6,%7}, {%8,%9}, {%0,%1,%2,%3};"
        : "+f"(d[0]), "+f"(d[1]), "+f"(d[2]), "+f"(d[3])
        : "r"(a0), "r"(a1), "r"(a2), "r"(a3), "r"(b0), "r"(b1));
}
__device__ __forceinline__ void sts_u16(uint32_t addr, unsigned short v) {
    asm volatile("st.shared.u16 [%0], %1;" :: "r"(addr), "h"(v) : "memory");
}
__device__ __forceinline__ uint32_t lds_u32(uint32_t addr) {
    uint32_t v;
    asm volatile("ld.shared.u32 %0, [%1];" : "=r"(v) : "r"(addr));
    return v;
}

// ---------------------------------------------------------------------------
__global__ __launch_bounds__(NTHREADS, 1) void fused_kernel(
    const float* __restrict__ query,
    const float* __restrict__ W1, const float* __restrict__ b1,
    const float* __restrict__ W2, const float* __restrict__ b2,
    const float* __restrict__ values,
    const float* __restrict__ keys,
    float* __restrict__ content,
    float* __restrict__ attn_out,
    int nrows, int ntiles)
{
    extern __shared__ char smem[];
    float* b1_s   = (float*)(smem + SO_B1);
    float* b2_s   = (float*)(smem + SO_B2);
    float* h_s    = (float*)(smem + SO_H);
    float* rs_s   = (float*)(smem + SO_RS);

    const uint32_t smem_base = smem_u32(smem);
    const uint32_t a_base = smem_base + SO_A;
    const uint32_t b_base = smem_base + SO_B;

    const int tid  = threadIdx.x;
    const int warp = tid >> 5;
    const int lane = tid & 31;

    // ---- one-time setup: weights/keys (padded for vector loads) ----
    {
        float* W1p = (float*)(smem + SO_W1P);
        for (int i = tid; i < HID * 20; i += NTHREADS) {
            int r = i / 20, d = i % 20;
            W1p[i] = (d < DQ) ? W1[r * DQ + d] : 0.f;
        }
        for (int i = tid; i < HID; i += NTHREADS) b1_s[i] = b1[i];
        float* W2r = (float*)(smem + SO_W2R);
        for (int i = tid; i < DK * 36; i += NTHREADS) {
            int r = i / 36, j = i % 36;
            W2r[i] = (j < HID) ? W2[r * HID + j] : 0.f;
        }
        for (int i = tid; i < DK; i += NTHREADS) b2_s[i] = b2[i];
        float* K12 = (float*)(smem + SO_KEYS);
        for (int i = tid; i < NS * 12; i += NTHREADS) {
            int k = i / 12, c = i % 12;
            K12[i] = (c < DK) ? keys[k * DK + c] : 0.f;
        }
        // Bn[n][k] fp16 (n-major transpose of values[k][n])
        for (int i = tid; i < NS * (DV / 2); i += NTHREADS) {
            const int k  = i / (DV / 2);
            const int np = i % (DV / 2);
            const float2 v = __ldg((const float2*)(values + k * DV + 2 * np));
            sts_u16(b_base + ((2 * np)     * BKS + k) * 2,
                    __half_as_ushort(__float2half_rn(v.x)));
            sts_u16(b_base + ((2 * np + 1) * BKS + k) * 2,
                    __half_as_ushort(__float2half_rn(v.y)));
        }
    }
    __syncthreads();

    for (int tile = blockIdx.x; tile < ntiles; tile += gridDim.x) {
        const long row0 = (long)tile * TILE_M;

        // ================= Phase A: projection + softmax ===================
        {
            float q8r[4][8];

            {   // ---- per-row projection: q8 for 4 rows ----
                const float4* w1v = (const float4*)(smem + SO_W1P + lane * 80);
                const float4 wa = w1v[0], wb = w1v[1], wc = w1v[2], wd2 = w1v[3];
                const float b1r = b1_s[lane];
                const int ci = lane & 7;
                const float b2r = b2_s[ci];
                const float4* w2v = (const float4*)(smem + SO_W2R + ci * 144);
                const float4* hv  = (const float4*)(h_s + warp * HID);

                #pragma unroll
                for (int rr = 0; rr < 4; rr++) {
                    const int  mloc = warp * 4 + rr;
                    const long row  = row0 + mloc;
                    const float2* xp = (const float2*)(query + row * DQ);
                    float xr[DQ];
                    #pragma unroll
                    for (int d = 0; d < 7; d++) {
                        float2 v = __ldg(&xp[d]);
                        xr[2 * d] = v.x; xr[2 * d + 1] = v.y;
                    }
                    float hj = b1r;
                    hj = fmaf(wa.x, xr[0], hj);  hj = fmaf(wa.y, xr[1], hj);
                    hj = fmaf(wa.z, xr[2], hj);  hj = fmaf(wa.w, xr[3], hj);
                    hj = fmaf(wb.x, xr[4], hj);  hj = fmaf(wb.y, xr[5], hj);
                    hj = fmaf(wb.z, xr[6], hj);  hj = fmaf(wb.w, xr[7], hj);
                    hj = fmaf(wc.x, xr[8], hj);  hj = fmaf(wc.y, xr[9], hj);
                    hj = fmaf(wc.z, xr[10], hj); hj = fmaf(wc.w, xr[11], hj);
                    hj = fmaf(wd2.x, xr[12], hj); hj = fmaf(wd2.y, xr[13], hj);
                    hj = 0.5f * hj * (1.0f + erff(hj * 0.7071067811865476f));
                    h_s[warp * HID + lane] = hj;
                    __syncwarp();

                    float q = b2r;
                    #pragma unroll
                    for (int j4 = 0; j4 < 8; j4++) {
                        const float4 h4 = hv[j4];
                        const float4 w4 = w2v[j4];
                        q = fmaf(w4.x, h4.x, q); q = fmaf(w4.y, h4.y, q);
                        q = fmaf(w4.z, h4.z, q); q = fmaf(w4.w, h4.w, q);
                    }
                    __syncwarp();
                    float ss = q * q;
                    ss += __shfl_xor_sync(0xffffffffu, ss, 1);
                    ss += __shfl_xor_sync(0xffffffffu, ss, 2);
                    ss += __shfl_xor_sync(0xffffffffu, ss, 4);
                    const float inv = 1.0f / fmaxf(sqrtf(ss), 1e-12f);
                    const float qn = q * inv;
                    #pragma unroll
                    for (int i = 0; i < 8; i++)
                        q8r[rr][i] = __shfl_sync(0xffffffffu, qn, i);
                }
            }

            // ---- t-loop: each key loaded once, used for 4 rows ----
            float ssum[4] = {0.f, 0.f, 0.f, 0.f};
            const uint32_t a_row_base = a_base + (warp * 4) * (AK * 2);
            #pragma unroll
            for (int t = 0; t < 8; t++) {
                const int k = lane + 32 * t;
                const float4* kv = (const float4*)(smem + SO_KEYS + k * 48);
                const float4 ka = kv[0];
                const float4 kb = kv[1];
                const bool valid = (k < NS);
                #pragma unroll
                for (int rr = 0; rr < 4; rr++) {
                    float s = q8r[rr][0] * ka.x;
                    s = fmaf(q8r[rr][1], ka.y, s);
                    s = fmaf(q8r[rr][2], ka.z, s);
                    s = fmaf(q8r[rr][3], ka.w, s);
                    s = fmaf(q8r[rr][4], kb.x, s);
                    s = fmaf(q8r[rr][5], kb.y, s);
                    s = fmaf(q8r[rr][6], kb.z, s);
                    s = fmaf(q8r[rr][7], kb.w, s);
                    float e = __expf(BETA * (s - 1.0f));
                    e = valid ? e : 0.f;
                    ssum[rr] += e;
                    if (valid)
                        sts_u16(a_row_base + rr * (AK * 2) + k * 2,
                                __half_as_ushort(__float2half_rn(e)));
                }
            }
            #pragma unroll
            for (int rr = 0; rr < 4; rr++) {
                #pragma unroll
                for (int o = 16; o > 0; o >>= 1)
                    ssum[rr] += __shfl_xor_sync(0xffffffffu, ssum[rr], o);
            }
            if (lane == 0) {
                rs_s[warp * 4 + 0] = ssum[0];
                rs_s[warp * 4 + 1] = ssum[1];
                rs_s[warp * 4 + 2] = ssum[2];
                rs_s[warp * 4 + 3] = ssum[3];
            }

            // ---- attn output: read back e, scale, store fp32 ----
            #pragma unroll
            for (int rr = 0; rr < 4; rr++) {
                const float invs = __fdividef(1.0f, ssum[rr]);
                float* arow = attn_out + (row0 + warp * 4 + rr) * NS;
                #pragma unroll
                for (int tp = 0; tp < 4; tp++) {
                    const int idx = lane + 32 * tp;   // u32 index: 2 halves
                    if (idx < NS / 2) {
                        const uint32_t v = lds_u32(a_row_base + rr * (AK * 2) + idx * 4);
                        const __half2 h2 = *(const __half2*)&v;
                        const float2 f = __half22float2(h2);
                        *(float2*)(arow + 2 * idx) = make_float2(f.x * invs, f.y * invs);
                    }
                }
            }
        }
        __syncthreads();

        // ===== Phase B: content = A(e) @ Bn^T, 32m x 32n warp tiles ========
        {
            const int m0 = (warp & 3) * 32;
            const int n0 = (warp >> 2) * 32;

            float acc[2][4][4];
            #pragma unroll
            for (int i = 0; i < 2; i++)
                #pragma unroll
                for (int t = 0; t < 4; t++)
                    #pragma unroll
                    for (int j = 0; j < 4; j++) acc[i][t][j] = 0.f;

            const uint32_t a_lane0 = a_base
                + ((m0 + (lane & 15)) * AK + (lane >> 4) * 8) * 2;
            const uint32_t a_lane1 = a_lane0 + 16 * AK * 2;
            const uint32_t b_lane = b_base
                + ((n0 + ((lane >> 4) << 3) + (lane & 7)) * BKS
                   + (((lane >> 3) & 1) * 8)) * 2;

            #pragma unroll
            for (int ks = 0; ks < NKSTEP; ks++) {
                uint32_t a0[4], a1[4];
                ldsm_x4(a0[0], a0[1], a0[2], a0[3], a_lane0 + ks * 32);
                ldsm_x4(a1[0], a1[1], a1[2], a1[3], a_lane1 + ks * 32);
                #pragma unroll
                for (int np = 0; np < 2; np++) {
                    uint32_t b0, b1, b2, b3;
                    ldsm_x4(b0, b1, b2, b3, b_lane + (np * 16 * BKS + ks * 16) * 2);
                    mma16816(acc[0][2 * np],     a0[0], a0[1], a0[2], a0[3], b0, b1);
                    mma16816(acc[0][2 * np + 1], a0[0], a0[1], a0[2], a0[3], b2, b3);
                    mma16816(acc[1][2 * np],     a1[0], a1[1], a1[2], a1[3], b0, b1);
                    mma16816(acc[1][2 * np + 1], a1[0], a1[1], a1[2], a1[3], b2, b3);
                }
            }

            // epilogue: scale by 1/rowsum, store
            #pragma unroll
            for (int i = 0; i < 2; i++) {
                const int lrA = m0 + i * 16 + (lane >> 2);
                const float invA = __fdividef(1.0f, rs_s[lrA]);
                const float invB = __fdividef(1.0f, rs_s[lrA + 8]);
                const long r0 = row0 + lrA;
                const int cofs = (lane & 3) * 2;
                #pragma unroll
                for (int t = 0; t < 4; t++) {
                    const int col = n0 + t * 8 + cofs;
                    *(float2*)(content + r0 * DV + col) =
                        make_float2(acc[i][t][0] * invA, acc[i][t][1] * invA);
                    *(float2*)(content + (r0 + 8) * DV + col) =
                        make_float2(acc[i][t][2] * invB, acc[i][t][3] * invB);
                }
            }
        }
        __syncthreads();   // A_s / rs_s fully consumed before next tile
    }
}

// ---------------------------------------------------------------------------
extern "C" void kernel_launch(void* const* d_in, const int* in_sizes, int n_in,
                              void* d_out, int out_size)
{
    const float* query  = (const float*)d_in[0];
    const float* W1     = (const float*)d_in[1];
    const float* b1     = (const float*)d_in[2];
    const float* W2     = (const float*)d_in[3];
    const float* b2     = (const float*)d_in[4];
    const float* values = (const float*)d_in[5];
    const float* keys   = (const float*)d_in[6];

    const int nrows  = in_sizes[0] / DQ;   // 262144
    const int ntiles = (nrows + TILE_M - 1) / TILE_M;

    float* out = (float*)d_out;
    float* content = out;
    float* attn;
    float* scratch;
    cudaGetSymbolAddress((void**)&scratch, g_attn_scratch);
    if ((long)out_size >= (long)nrows * (DV + NS)) {
        attn = out + (long)nrows * DV;
    } else {
        attn = scratch;
    }

    cudaFuncSetAttribute(fused_kernel, cudaFuncAttributeMaxDynamicSharedMemorySize,
                         SMEM_TOTAL);

    fused_kernel<<<152, NTHREADS, SMEM_TOTAL>>>(
        query, W1, b1, W2, b2, values, keys, content, attn, nrows, ntiles);
}